// round 1
// baseline (speedup 1.0000x reference)
#include <cuda_runtime.h>
#include <math.h>

#define NPOS 4096
#define NC   192

// ---------------- scratch (static device globals; no allocation) -------------
__device__ float g_qkv[NPOS * 576];   // (pos, 576) pos-major
__device__ float g_o  [NPOS * 192];   // (pos, 192) pos-major
__device__ float g_x2 [192 * NPOS];   // (C, pos)  channel-major
__device__ float g_m  [768 * NPOS];   // (768, pos)
__device__ float g_ws [768 * 192];    // scaled weights (reused)
__device__ float g_sums[2 * 192];     // per-channel sum / sumsq
__device__ float g_mult[192];         // scale*gamma/rms

// ---------------- per-channel sum & sumsq over 4096 spatial elems ------------
__global__ void colstats_kernel(const float* __restrict__ x) {
    int c = blockIdx.x;
    const float* p = x + c * NPOS;
    float s = 0.f, s2 = 0.f;
    for (int i = threadIdx.x; i < NPOS; i += 256) {
        float v = p[i];
        s += v;
        s2 = fmaf(v, v, s2);
    }
    __shared__ float sh0[256], sh1[256];
    sh0[threadIdx.x] = s; sh1[threadIdx.x] = s2;
    __syncthreads();
    for (int o = 128; o > 0; o >>= 1) {
        if (threadIdx.x < o) {
            sh0[threadIdx.x] += sh0[threadIdx.x + o];
            sh1[threadIdx.x] += sh1[threadIdx.x + o];
        }
        __syncthreads();
    }
    if (threadIdx.x == 0) {
        g_sums[c]       = sh0[0];
        g_sums[192 + c] = sh1[0];
    }
}

// ---------------- tiny MLP -> per-channel multiplier scale*gamma/rms ---------
__global__ void gamma_kernel(const float* __restrict__ w1, const float* __restrict__ b1,
                             const float* __restrict__ w2, const float* __restrict__ b2,
                             const float* __restrict__ scale) {
    __shared__ float stats[192];
    __shared__ float h[384];
    int t = threadIdx.x;   // 384 threads
    if (t < 192) stats[t] = g_sums[t] * (1.0f / 4096.0f);
    __syncthreads();
    float acc = b1[t];
    #pragma unroll 4
    for (int c = 0; c < 192; c++) acc = fmaf(stats[c], w1[t * 192 + c], acc);
    h[t] = fmaxf(acc, 0.f);
    __syncthreads();
    if (t < 192) {
        float a = b2[t];
        #pragma unroll 4
        for (int j = 0; j < 384; j++) a = fmaf(h[j], w2[t * 384 + j], a);
        float gamma = 1.f / (1.f + expf(-a));
        float rms = sqrtf(g_sums[192 + t] * (1.0f / 4096.0f) + 1e-6f);
        g_mult[t] = scale[t] * gamma / rms;
    }
}

// ---------------- fold per-channel multiplier into weight columns ------------
__global__ void scalew_kernel(const float* __restrict__ w, float* __restrict__ out, int total) {
    int i = blockIdx.x * 256 + threadIdx.x;
    if (i < total) out[i] = w[i] * g_mult[i % 192];
}

// ---------------- generic GEMM: out = epi(W(Co,Ci) @ X(Ci,N) + bias) ---------
// XN:  X stored as (N,Ci) instead of (Ci,N)
// EPI: 0 = none, 1 = exact gelu, 2 = + res (res in (Co,N) layout)
// outNCo: write (N,Co) instead of (Co,N)
template <bool XN, int EPI>
__global__ void __launch_bounds__(256)
gemm_kernel(const float* __restrict__ W, const float* __restrict__ X,
            const float* __restrict__ bias, const float* __restrict__ res,
            float* __restrict__ out, int Co, int Ci, int N, int outNCo) {
    __shared__ float sW[16][68];  // [k][m]
    __shared__ float sX[16][68];  // [k][n]

    const int bn = blockIdx.x * 64;
    const int bm = blockIdx.y * 64;
    const int tid = threadIdx.x;
    const int tx = tid & 15;        // n group
    const int ty = tid >> 4;        // m group

    float acc[4][4];
    #pragma unroll
    for (int i = 0; i < 4; i++)
        #pragma unroll
        for (int j = 0; j < 4; j++) acc[i][j] = 0.f;

    for (int kk = 0; kk < Ci; kk += 16) {
        // stage W tile: sW[k][m] = W[(bm+m)*Ci + kk+k]
        {
            int k = tid & 15, m = tid >> 4;
            #pragma unroll
            for (int r = 0; r < 4; r++)
                sW[k][m + r * 16] = W[(size_t)(bm + m + r * 16) * Ci + kk + k];
        }
        // stage X tile: sX[k][n]
        if (XN) {
            int k = tid & 15, n = tid >> 4;
            #pragma unroll
            for (int r = 0; r < 4; r++)
                sX[k][n + r * 16] = X[(size_t)(bn + n + r * 16) * Ci + kk + k];
        } else {
            int n = tid & 63, k = tid >> 6;
            #pragma unroll
            for (int r = 0; r < 4; r++)
                sX[k + r * 4][n] = X[(size_t)(kk + k + r * 4) * N + bn + n];
        }
        __syncthreads();

        #pragma unroll
        for (int k = 0; k < 16; k++) {
            float4 a = *(const float4*)&sW[k][ty * 4];
            float4 b = *(const float4*)&sX[k][tx * 4];
            acc[0][0] = fmaf(a.x, b.x, acc[0][0]); acc[0][1] = fmaf(a.x, b.y, acc[0][1]);
            acc[0][2] = fmaf(a.x, b.z, acc[0][2]); acc[0][3] = fmaf(a.x, b.w, acc[0][3]);
            acc[1][0] = fmaf(a.y, b.x, acc[1][0]); acc[1][1] = fmaf(a.y, b.y, acc[1][1]);
            acc[1][2] = fmaf(a.y, b.z, acc[1][2]); acc[1][3] = fmaf(a.y, b.w, acc[1][3]);
            acc[2][0] = fmaf(a.z, b.x, acc[2][0]); acc[2][1] = fmaf(a.z, b.y, acc[2][1]);
            acc[2][2] = fmaf(a.z, b.z, acc[2][2]); acc[2][3] = fmaf(a.z, b.w, acc[2][3]);
            acc[3][0] = fmaf(a.w, b.x, acc[3][0]); acc[3][1] = fmaf(a.w, b.y, acc[3][1]);
            acc[3][2] = fmaf(a.w, b.z, acc[3][2]); acc[3][3] = fmaf(a.w, b.w, acc[3][3]);
        }
        __syncthreads();
    }

    #pragma unroll
    for (int i = 0; i < 4; i++) {
        int m = bm + ty * 4 + i;
        float bv = bias[m];
        #pragma unroll
        for (int j = 0; j < 4; j++) {
            int n = bn + tx * 4 + j;
            float v = acc[i][j] + bv;
            if (EPI == 1) v = v * 0.5f * (1.f + erff(v * 0.70710678118654752f));
            if (EPI == 2) v += res[(size_t)m * N + n];
            if (outNCo) out[(size_t)n * Co + m] = v;
            else        out[(size_t)m * N + n] = v;
        }
    }
}

// ---------------- 3D neighborhood attention ----------------------------------
// One block per voxel (192 threads = 6 warps = 6 heads), lanes = 32 head dims.
__global__ void __launch_bounds__(192) attn_kernel(const float* __restrict__ qkv,
                                                   float* __restrict__ o) {
    const int pos = blockIdx.x;
    const int w = pos & 15, hh = (pos >> 4) & 15, d = pos >> 8;
    __shared__ int nidx[125];
    const int t = threadIdx.x;
    if (t < 125) {
        int a = t / 25, b = (t / 5) % 5, c = t % 5;
        int sd = min(max(d - 2, 0), 11);
        int sh = min(max(hh - 2, 0), 11);
        int sw = min(max(w - 2, 0), 11);
        nidx[t] = (((sd + a) << 4) + (sh + b)) * 16 + (sw + c);
    }
    __syncthreads();

    const int warp = t >> 5, lane = t & 31;
    const unsigned FULL = 0xffffffffu;
    const int hb = warp * 32;

    float qv = qkv[(size_t)pos * 576 + hb + lane] * 0.17677669529663687f;  // 1/sqrt(32)

    float sc[4];
    // -------- pass 1: scores via warp reduce, scatter to owning lane --------
    #pragma unroll
    for (int slot = 0; slot < 4; slot++) {
        int jmax = (slot == 3) ? 29 : 32;
        float mys = -1e30f;
        for (int jj = 0; jj < jmax; jj++) {
            int np = nidx[slot * 32 + jj];
            float kk = qkv[(size_t)np * 576 + 192 + hb + lane];
            float s = qv * kk;
            s += __shfl_xor_sync(FULL, s, 16);
            s += __shfl_xor_sync(FULL, s, 8);
            s += __shfl_xor_sync(FULL, s, 4);
            s += __shfl_xor_sync(FULL, s, 2);
            s += __shfl_xor_sync(FULL, s, 1);
            if (jj == lane) mys = s;
        }
        sc[slot] = mys;
    }

    // -------- softmax over 125 entries (4 per lane, last slot partial) ------
    float mx = fmaxf(fmaxf(sc[0], sc[1]), fmaxf(sc[2], sc[3]));
    #pragma unroll
    for (int off = 16; off; off >>= 1) mx = fmaxf(mx, __shfl_xor_sync(FULL, mx, off));
    float tot = 0.f;
    #pragma unroll
    for (int i = 0; i < 4; i++) {
        sc[i] = __expf(sc[i] - mx);   // exp(-1e30 - mx) == 0 for invalid slots
        tot += sc[i];
    }
    #pragma unroll
    for (int off = 16; off; off >>= 1) tot += __shfl_xor_sync(FULL, tot, off);
    float inv = 1.f / tot;

    // -------- pass 2: weighted sum of V -------------------------------------
    float oa = 0.f;
    #pragma unroll
    for (int slot = 0; slot < 4; slot++) {
        int jmax = (slot == 3) ? 29 : 32;
        for (int jj = 0; jj < jmax; jj++) {
            float pj = __shfl_sync(FULL, sc[slot], jj);
            int np = nidx[slot * 32 + jj];
            float v = qkv[(size_t)np * 576 + 384 + hb + lane];
            oa = fmaf(pj, v, oa);
        }
    }
    o[(size_t)pos * 192 + hb + lane] = oa * inv;
}

// ---------------- orchestration ----------------------------------------------
extern "C" void kernel_launch(void* const* d_in, const int* in_sizes, int n_in,
                              void* d_out, int out_size) {
    const float* x      = (const float*)d_in[0];
    const float* scale1 = (const float*)d_in[1];
    const float* n1_w1  = (const float*)d_in[2];
    const float* n1_b1  = (const float*)d_in[3];
    const float* n1_w2  = (const float*)d_in[4];
    const float* n1_b2  = (const float*)d_in[5];
    const float* qkv_w  = (const float*)d_in[6];
    const float* qkv_b  = (const float*)d_in[7];
    const float* proj_w = (const float*)d_in[8];
    const float* proj_b = (const float*)d_in[9];
    const float* scale2 = (const float*)d_in[10];
    const float* n2_w1  = (const float*)d_in[11];
    const float* n2_b1  = (const float*)d_in[12];
    const float* n2_w2  = (const float*)d_in[13];
    const float* n2_b2  = (const float*)d_in[14];
    const float* mlp_w1 = (const float*)d_in[15];
    const float* mlp_b1 = (const float*)d_in[16];
    const float* mlp_w2 = (const float*)d_in[17];
    const float* mlp_b2 = (const float*)d_in[18];
    float* out = (float*)d_out;

    float *qkv, *ob, *x2, *mb, *ws;
    cudaGetSymbolAddress((void**)&qkv, g_qkv);
    cudaGetSymbolAddress((void**)&ob,  g_o);
    cudaGetSymbolAddress((void**)&x2,  g_x2);
    cudaGetSymbolAddress((void**)&mb,  g_m);
    cudaGetSymbolAddress((void**)&ws,  g_ws);

    // ---- stage A: adaRMSNorm1 folded into qkv weights ----
    colstats_kernel<<<192, 256>>>(x);
    gamma_kernel<<<1, 384>>>(n1_w1, n1_b1, n1_w2, n1_b2, scale1);
    scalew_kernel<<<(576 * 192 + 255) / 256, 256>>>(qkv_w, ws, 576 * 192);

    // qkv: (576,192)@(192,4096) -> (4096,576) pos-major
    gemm_kernel<false, 0><<<dim3(64, 9), 256>>>(ws, x, qkv_b, nullptr, qkv, 576, 192, NPOS, 1);

    // attention -> O (4096,192) pos-major
    attn_kernel<<<NPOS, 192>>>(qkv, ob);

    // proj + residual: x2 (C,N) = proj_w @ O^T + proj_b + x
    gemm_kernel<true, 2><<<dim3(64, 3), 256>>>(proj_w, ob, proj_b, x, x2, 192, 192, NPOS, 0);

    // ---- stage B: adaRMSNorm2 folded into mlp_w1 ----
    colstats_kernel<<<192, 256>>>(x2);
    gamma_kernel<<<1, 384>>>(n2_w1, n2_b1, n2_w2, n2_b2, scale2);
    scalew_kernel<<<(768 * 192 + 255) / 256, 256>>>(mlp_w1, ws, 768 * 192);

    // mlp1 + gelu: (768,192)@(192,4096) -> (768,4096)
    gemm_kernel<false, 1><<<dim3(64, 12), 256>>>(ws, x2, mlp_b1, nullptr, mb, 768, 192, NPOS, 0);

    // mlp2 + residual -> final output (C,N) == (1,192,16,16,16)
    gemm_kernel<false, 2><<<dim3(64, 3), 256>>>(mlp_w2, mb, mlp_b2, x2, out, 192, 768, NPOS, 0);
}

// round 2
// speedup vs baseline: 1.2316x; 1.2316x over previous
#include <cuda_runtime.h>
#include <math.h>

#define NPOS 4096

// ---------------- scratch (static device globals; no allocation) -------------
__device__ float g_qkv[NPOS * 576];   // (pos, 576) pos-major
__device__ float g_o  [NPOS * 192];   // (pos, 192) pos-major
__device__ float g_x2 [192 * NPOS];   // (C, pos)  channel-major
__device__ float g_m  [768 * NPOS];   // (768, pos)
__device__ float g_sums[2 * 192];     // per-channel sum / sumsq
__device__ float g_mult[192];         // scale*gamma/rms

// ---------------- f32x2 packed math helpers (sm_10x) --------------------------
__device__ __forceinline__ unsigned long long dupf2(float a) {
    unsigned long long d;
    asm("mov.b64 %0, {%1, %1};" : "=l"(d) : "f"(a));
    return d;
}
__device__ __forceinline__ void fmaf2(unsigned long long& d, unsigned long long a,
                                      unsigned long long b) {
    asm("fma.rn.f32x2 %0, %1, %2, %0;" : "+l"(d) : "l"(a), "l"(b));
}
__device__ __forceinline__ float2 unpackf2(unsigned long long d) {
    float2 r;
    asm("mov.b64 {%0, %1}, %2;" : "=f"(r.x), "=f"(r.y) : "l"(d));
    return r;
}

// ---------------- per-channel sum & sumsq over 4096 spatial elems ------------
__global__ void colstats_kernel(const float* __restrict__ x) {
    int c = blockIdx.x;
    const float* p = x + c * NPOS;
    float s = 0.f, s2 = 0.f;
    for (int i = threadIdx.x; i < NPOS; i += 256) {
        float v = p[i];
        s += v;
        s2 = fmaf(v, v, s2);
    }
    __shared__ float sh0[256], sh1[256];
    sh0[threadIdx.x] = s; sh1[threadIdx.x] = s2;
    __syncthreads();
    for (int o = 128; o > 0; o >>= 1) {
        if (threadIdx.x < o) {
            sh0[threadIdx.x] += sh0[threadIdx.x + o];
            sh1[threadIdx.x] += sh1[threadIdx.x + o];
        }
        __syncthreads();
    }
    if (threadIdx.x == 0) {
        g_sums[c]       = sh0[0];
        g_sums[192 + c] = sh1[0];
    }
}

// ---------------- tiny MLP -> per-channel multiplier scale*gamma/rms ---------
__global__ void gamma_kernel(const float* __restrict__ w1, const float* __restrict__ b1,
                             const float* __restrict__ w2, const float* __restrict__ b2,
                             const float* __restrict__ scale) {
    __shared__ float stats[192];
    __shared__ float h[384];
    int t = threadIdx.x;   // 384 threads
    if (t < 192) stats[t] = g_sums[t] * (1.0f / 4096.0f);
    __syncthreads();
    float acc = b1[t];
    #pragma unroll 4
    for (int c = 0; c < 192; c++) acc = fmaf(stats[c], w1[t * 192 + c], acc);
    h[t] = fmaxf(acc, 0.f);
    __syncthreads();
    if (t < 192) {
        float a = b2[t];
        #pragma unroll 4
        for (int j = 0; j < 384; j++) a = fmaf(h[j], w2[t * 384 + j], a);
        float gamma = 1.f / (1.f + expf(-a));
        float rms = sqrtf(g_sums[192 + t] * (1.0f / 4096.0f) + 1e-6f);
        g_mult[t] = scale[t] * gamma / rms;
    }
}

// ---------------- generic GEMM: out = epi(W(Co,Ci) @ X(Ci,N) + bias) ---------
// XN:  X stored as (N,Ci) instead of (Ci,N)
// EPI: 0 = none, 1 = exact gelu, 2 = + res (res in (Co,N) layout)
// WS:  scale W columns by g_mult[k] while staging (adaRMSNorm fold)
// outNCo: write (N,Co) instead of (Co,N)
template <bool XN, int EPI, bool WS>
__global__ void __launch_bounds__(256)
gemm_kernel(const float* __restrict__ W, const float* __restrict__ X,
            const float* __restrict__ bias, const float* __restrict__ res,
            float* __restrict__ out, int Co, int Ci, int N, int outNCo) {
    __shared__ float sW[16][68];  // [k][m]
    __shared__ float sX[16][68];  // [k][n]

    const int bn = blockIdx.x * 64;
    const int bm = blockIdx.y * 64;
    const int tid = threadIdx.x;
    const int tx = tid & 15;        // n group
    const int ty = tid >> 4;        // m group

    unsigned long long acc[4][2];   // [m][n-pair] packed f32x2
    #pragma unroll
    for (int i = 0; i < 4; i++) { acc[i][0] = 0ull; acc[i][1] = 0ull; }

    for (int kk = 0; kk < Ci; kk += 16) {
        // stage W tile: sW[k][m] = W[(bm+m)*Ci + kk+k]  (* g_mult[kk+k] if WS)
        {
            int k = tid & 15, m = tid >> 4;
            float sc = WS ? g_mult[kk + k] : 1.f;
            #pragma unroll
            for (int r = 0; r < 4; r++) {
                float v = W[(size_t)(bm + m + r * 16) * Ci + kk + k];
                sW[k][m + r * 16] = WS ? v * sc : v;
            }
        }
        // stage X tile: sX[k][n]
        if (XN) {
            int k = tid & 15, n = tid >> 4;
            #pragma unroll
            for (int r = 0; r < 4; r++)
                sX[k][n + r * 16] = X[(size_t)(bn + n + r * 16) * Ci + kk + k];
        } else {
            int n = tid & 63, k = tid >> 6;
            #pragma unroll
            for (int r = 0; r < 4; r++)
                sX[k + r * 4][n] = X[(size_t)(kk + k + r * 4) * N + bn + n];
        }
        __syncthreads();

        #pragma unroll
        for (int k = 0; k < 16; k++) {
            float4 a = *(const float4*)&sW[k][ty * 4];
            const unsigned long long* bp = (const unsigned long long*)&sX[k][tx * 4];
            unsigned long long b01 = bp[0], b23 = bp[1];
            unsigned long long ax = dupf2(a.x), ay = dupf2(a.y),
                               az = dupf2(a.z), aw = dupf2(a.w);
            fmaf2(acc[0][0], ax, b01); fmaf2(acc[0][1], ax, b23);
            fmaf2(acc[1][0], ay, b01); fmaf2(acc[1][1], ay, b23);
            fmaf2(acc[2][0], az, b01); fmaf2(acc[2][1], az, b23);
            fmaf2(acc[3][0], aw, b01); fmaf2(acc[3][1], aw, b23);
        }
        __syncthreads();
    }

    #pragma unroll
    for (int i = 0; i < 4; i++) {
        int m = bm + ty * 4 + i;
        float bv = bias[m];
        #pragma unroll
        for (int p = 0; p < 2; p++) {
            float2 u = unpackf2(acc[i][p]);
            #pragma unroll
            for (int e = 0; e < 2; e++) {
                int n = bn + tx * 4 + p * 2 + e;
                float v = (e ? u.y : u.x) + bv;
                if (EPI == 1) v = v * 0.5f * (1.f + erff(v * 0.70710678118654752f));
                if (EPI == 2) v += res[(size_t)m * N + n];
                if (outNCo) out[(size_t)n * Co + m] = v;
                else        out[(size_t)m * N + n] = v;
            }
        }
    }
}

// ---------------- 3D neighborhood attention (tiled) ---------------------------
// block = (4x4x4 voxel tile, one head). 256 threads = 64 voxels x 4 ch-quarters.
// 8^3 neighborhood-union K (then V, buffer reused) staged in dynamic smem.
#define KV_STRIDE 36
__device__ __forceinline__ void load_kv_tile(float* sKV, const float* __restrict__ src,
                                             int Bd, int Bh, int Bw, int tid) {
    // src points at qkv + (192 or 384) + head*32 ; rows are 576-float strided
    #pragma unroll
    for (int it = 0; it < 16; it++) {
        int i = tid + it * 256;              // 4096 float4-groups total
        int row = i >> 3, g = i & 7;         // 512 rows x 8 groups of 4 ch
        int rd = row >> 6, rh = (row >> 3) & 7, rw = row & 7;
        int gpos = ((Bd + rd) << 8) + ((Bh + rh) << 4) + (Bw + rw);
        float4 val = *(const float4*)(src + (size_t)gpos * 576 + g * 4);
        int q = g >> 1, c2 = (g & 1) * 4;
        *(float4*)&sKV[row * KV_STRIDE + ((q ^ (row & 3)) << 3) + c2] = val;
    }
}

__global__ void __launch_bounds__(256) attn_kernel(const float* __restrict__ qkv,
                                                   float* __restrict__ o) {
    extern __shared__ float sKV[];   // 512 * 36 floats = 73728 B
    const int tile = blockIdx.x, head = blockIdx.y;
    const int Td = ((tile >> 4) & 3) * 4, Th = ((tile >> 2) & 3) * 4, Tw = (tile & 3) * 4;
    const int Bd = min(max(Td - 2, 0), 8);
    const int Bh = min(max(Th - 2, 0), 8);
    const int Bw = min(max(Tw - 2, 0), 8);

    const int tid = threadIdx.x;
    const int quarter = tid & 3, vox = tid >> 2;
    const int aw = vox & 3, ah = (vox >> 2) & 3, ad = vox >> 4;
    const int vd = Td + ad, vh = Th + ah, vw = Tw + aw;
    const int gv = (vd << 8) + (vh << 4) + vw;
    const int ld = min(max(vd - 2, 0), 11) - Bd;
    const int lh = min(max(vh - 2, 0), 11) - Bh;
    const int lw = min(max(vw - 2, 0), 11) - Bw;
    const int rbase = ld * 64 + lh * 8 + lw;
    const unsigned FULL = 0xffffffffu;
    const int lane = tid & 31;

    // Q (8 channels per thread), pre-scaled
    float q[8];
    {
        const float* qp = qkv + (size_t)gv * 576 + head * 32 + quarter * 8;
        #pragma unroll
        for (int c = 0; c < 8; c++) q[c] = qp[c] * 0.17677669529663687f;
    }

    // ---- stage K, compute scores ----
    load_kv_tile(sKV, qkv + 192 + head * 32, Bd, Bh, Bw, tid);
    __syncthreads();

    float sc[32];
    #pragma unroll
    for (int i = 0; i < 32; i++) sc[i] = -1e30f;

    #pragma unroll
    for (int j = 0; j < 125; j++) {
        const int a = j / 25, b = (j / 5) % 5, c5 = j % 5;
        int row = rbase + a * 64 + b * 8 + c5;
        int cb = row * KV_STRIDE + ((quarter ^ (row & 3)) << 3);
        float4 k0 = *(const float4*)&sKV[cb];
        float4 k1 = *(const float4*)&sKV[cb + 4];
        float p = q[0] * k0.x;
        p = fmaf(q[1], k0.y, p); p = fmaf(q[2], k0.z, p); p = fmaf(q[3], k0.w, p);
        p = fmaf(q[4], k1.x, p); p = fmaf(q[5], k1.y, p);
        p = fmaf(q[6], k1.z, p); p = fmaf(q[7], k1.w, p);
        p += __shfl_xor_sync(FULL, p, 1);
        p += __shfl_xor_sync(FULL, p, 2);
        if ((j & 3) == quarter) sc[j >> 2] = p;
    }

    // ---- softmax across 4-lane quarter groups ----
    float mx = -1e30f;
    #pragma unroll
    for (int i = 0; i < 32; i++) mx = fmaxf(mx, sc[i]);
    mx = fmaxf(mx, __shfl_xor_sync(FULL, mx, 1));
    mx = fmaxf(mx, __shfl_xor_sync(FULL, mx, 2));
    float tot = 0.f;
    #pragma unroll
    for (int i = 0; i < 32; i++) { sc[i] = __expf(sc[i] - mx); tot += sc[i]; }
    tot += __shfl_xor_sync(FULL, tot, 1);
    tot += __shfl_xor_sync(FULL, tot, 2);
    float inv = 1.f / tot;

    // ---- stage V (reuse buffer), accumulate output ----
    __syncthreads();
    load_kv_tile(sKV, qkv + 384 + head * 32, Bd, Bh, Bw, tid);
    __syncthreads();

    float o8[8] = {0.f, 0.f, 0.f, 0.f, 0.f, 0.f, 0.f, 0.f};
    #pragma unroll
    for (int j = 0; j < 125; j++) {
        const int a = j / 25, b = (j / 5) % 5, c5 = j % 5;
        float p = __shfl_sync(FULL, sc[j >> 2], (lane & ~3) | (j & 3));
        int row = rbase + a * 64 + b * 8 + c5;
        int cb = row * KV_STRIDE + ((quarter ^ (row & 3)) << 3);
        float4 v0 = *(const float4*)&sKV[cb];
        float4 v1 = *(const float4*)&sKV[cb + 4];
        o8[0] = fmaf(p, v0.x, o8[0]); o8[1] = fmaf(p, v0.y, o8[1]);
        o8[2] = fmaf(p, v0.z, o8[2]); o8[3] = fmaf(p, v0.w, o8[3]);
        o8[4] = fmaf(p, v1.x, o8[4]); o8[5] = fmaf(p, v1.y, o8[5]);
        o8[6] = fmaf(p, v1.z, o8[6]); o8[7] = fmaf(p, v1.w, o8[7]);
    }
    float* op = o + (size_t)gv * 192 + head * 32 + quarter * 8;
    #pragma unroll
    for (int c = 0; c < 8; c++) op[c] = o8[c] * inv;
}

// ---------------- orchestration ----------------------------------------------
extern "C" void kernel_launch(void* const* d_in, const int* in_sizes, int n_in,
                              void* d_out, int out_size) {
    const float* x      = (const float*)d_in[0];
    const float* scale1 = (const float*)d_in[1];
    const float* n1_w1  = (const float*)d_in[2];
    const float* n1_b1  = (const float*)d_in[3];
    const float* n1_w2  = (const float*)d_in[4];
    const float* n1_b2  = (const float*)d_in[5];
    const float* qkv_w  = (const float*)d_in[6];
    const float* qkv_b  = (const float*)d_in[7];
    const float* proj_w = (const float*)d_in[8];
    const float* proj_b = (const float*)d_in[9];
    const float* scale2 = (const float*)d_in[10];
    const float* n2_w1  = (const float*)d_in[11];
    const float* n2_b1  = (const float*)d_in[12];
    const float* n2_w2  = (const float*)d_in[13];
    const float* n2_b2  = (const float*)d_in[14];
    const float* mlp_w1 = (const float*)d_in[15];
    const float* mlp_b1 = (const float*)d_in[16];
    const float* mlp_w2 = (const float*)d_in[17];
    const float* mlp_b2 = (const float*)d_in[18];
    float* out = (float*)d_out;

    float *qkv, *ob, *x2, *mb;
    cudaGetSymbolAddress((void**)&qkv, g_qkv);
    cudaGetSymbolAddress((void**)&ob,  g_o);
    cudaGetSymbolAddress((void**)&x2,  g_x2);
    cudaGetSymbolAddress((void**)&mb,  g_m);

    cudaFuncSetAttribute(attn_kernel, cudaFuncAttributeMaxDynamicSharedMemorySize,
                         512 * KV_STRIDE * 4);

    // ---- stage A: adaRMSNorm1 folded into qkv GEMM weight staging ----
    colstats_kernel<<<192, 256>>>(x);
    gamma_kernel<<<1, 384>>>(n1_w1, n1_b1, n1_w2, n1_b2, scale1);

    // qkv: (576,192)@(192,4096) -> (4096,576) pos-major
    gemm_kernel<false, 0, true><<<dim3(64, 9), 256>>>(qkv_w, x, qkv_b, nullptr, qkv, 576, 192, NPOS, 1);

    // attention -> O (4096,192) pos-major
    attn_kernel<<<dim3(64, 6), 256, 512 * KV_STRIDE * 4>>>(qkv, ob);

    // proj + residual: x2 (C,N) = proj_w @ O^T + proj_b + x
    gemm_kernel<true, 2, false><<<dim3(64, 3), 256>>>(proj_w, ob, proj_b, x, x2, 192, 192, NPOS, 0);

    // ---- stage B: adaRMSNorm2 folded into mlp1 GEMM weight staging ----
    colstats_kernel<<<192, 256>>>(x2);
    gamma_kernel<<<1, 384>>>(n2_w1, n2_b1, n2_w2, n2_b2, scale2);

    // mlp1 + gelu: (768,192)@(192,4096) -> (768,4096)
    gemm_kernel<false, 1, true><<<dim3(64, 12), 256>>>(mlp_w1, x2, mlp_b1, nullptr, mb, 768, 192, NPOS, 0);

    // mlp2 + residual -> final output (C,N) == (1,192,16,16,16)
    gemm_kernel<false, 2, false><<<dim3(64, 3), 256>>>(mlp_w2, mb, mlp_b2, x2, out, 192, 768, NPOS, 0);
}

// round 3
// speedup vs baseline: 2.1262x; 1.7264x over previous
#include <cuda_runtime.h>
#include <math.h>

#define NPOS 4096
#define FULLM 0xffffffffu

// ---------------- scratch (static device globals; no allocation) -------------
__device__ float g_qkv[NPOS * 576];   // (pos, 576) pos-major
__device__ float g_o  [NPOS * 192];   // (pos, 192) pos-major
__device__ float g_x2 [192 * NPOS];   // (C, pos)  channel-major
__device__ float g_m  [768 * NPOS];   // (768, pos)
__device__ float g_sums[2 * 192];     // per-channel sum / sumsq
__device__ float g_mult[192];         // scale*gamma/rms

// ---------------- f32x2 packed math helpers (sm_10x) --------------------------
__device__ __forceinline__ unsigned long long dupf2(float a) {
    unsigned long long d;
    asm("mov.b64 %0, {%1, %1};" : "=l"(d) : "f"(a));
    return d;
}
__device__ __forceinline__ void fmaf2(unsigned long long& d, unsigned long long a,
                                      unsigned long long b) {
    asm("fma.rn.f32x2 %0, %1, %2, %0;" : "+l"(d) : "l"(a), "l"(b));
}
__device__ __forceinline__ float2 unpackf2(unsigned long long d) {
    float2 r;
    asm("mov.b64 {%0, %1}, %2;" : "=f"(r.x), "=f"(r.y) : "l"(d));
    return r;
}

// ---------------- per-channel sum & sumsq over 4096 spatial elems ------------
__global__ void colstats_kernel(const float* __restrict__ x) {
    int c = blockIdx.x;
    const float* p = x + c * NPOS;
    float s = 0.f, s2 = 0.f;
    for (int i = threadIdx.x; i < NPOS; i += 256) {
        float v = p[i];
        s += v;
        s2 = fmaf(v, v, s2);
    }
    __shared__ float sh0[256], sh1[256];
    sh0[threadIdx.x] = s; sh1[threadIdx.x] = s2;
    __syncthreads();
    for (int o = 128; o > 0; o >>= 1) {
        if (threadIdx.x < o) {
            sh0[threadIdx.x] += sh0[threadIdx.x + o];
            sh1[threadIdx.x] += sh1[threadIdx.x + o];
        }
        __syncthreads();
    }
    if (threadIdx.x == 0) {
        g_sums[c]       = sh0[0];
        g_sums[192 + c] = sh1[0];
    }
}

// ---------------- tiny MLP -> per-channel multiplier scale*gamma/rms ---------
// 384 threads = 12 warps. Warp-cooperative coalesced dot products.
// Also zeroes g_sums at the end (so the next stats producer can atomicAdd).
__global__ void gamma_kernel(const float* __restrict__ w1, const float* __restrict__ b1,
                             const float* __restrict__ w2, const float* __restrict__ b2,
                             const float* __restrict__ scale) {
    __shared__ float stats[192];
    __shared__ float h[384];
    const int t = threadIdx.x, warp = t >> 5, lane = t & 31;
    if (t < 192) stats[t] = g_sums[t] * (1.0f / 4096.0f);
    __syncthreads();

    // layer 1: 384 outputs, warp w -> outputs [w*32, w*32+32), 4 at a time
    #pragma unroll
    for (int g = 0; g < 8; g++) {
        int ob = warp * 32 + g * 4;
        float acc0 = 0.f, acc1 = 0.f, acc2 = 0.f, acc3 = 0.f;
        #pragma unroll
        for (int j = 0; j < 6; j++) {
            float sv = stats[lane + j * 32];
            acc0 = fmaf(sv, w1[(ob + 0) * 192 + lane + j * 32], acc0);
            acc1 = fmaf(sv, w1[(ob + 1) * 192 + lane + j * 32], acc1);
            acc2 = fmaf(sv, w1[(ob + 2) * 192 + lane + j * 32], acc2);
            acc3 = fmaf(sv, w1[(ob + 3) * 192 + lane + j * 32], acc3);
        }
        #pragma unroll
        for (int off = 16; off; off >>= 1) {
            acc0 += __shfl_xor_sync(FULLM, acc0, off);
            acc1 += __shfl_xor_sync(FULLM, acc1, off);
            acc2 += __shfl_xor_sync(FULLM, acc2, off);
            acc3 += __shfl_xor_sync(FULLM, acc3, off);
        }
        if (lane == 0) {
            h[ob + 0] = fmaxf(acc0 + b1[ob + 0], 0.f);
            h[ob + 1] = fmaxf(acc1 + b1[ob + 1], 0.f);
            h[ob + 2] = fmaxf(acc2 + b1[ob + 2], 0.f);
            h[ob + 3] = fmaxf(acc3 + b1[ob + 3], 0.f);
        }
    }
    __syncthreads();

    // layer 2: 192 outputs, warps 0..5
    if (warp < 6) {
        #pragma unroll
        for (int g = 0; g < 8; g++) {
            int ob = warp * 32 + g * 4;
            float acc0 = 0.f, acc1 = 0.f, acc2 = 0.f, acc3 = 0.f;
            #pragma unroll
            for (int j = 0; j < 12; j++) {
                float hv = h[lane + j * 32];
                acc0 = fmaf(hv, w2[(ob + 0) * 384 + lane + j * 32], acc0);
                acc1 = fmaf(hv, w2[(ob + 1) * 384 + lane + j * 32], acc1);
                acc2 = fmaf(hv, w2[(ob + 2) * 384 + lane + j * 32], acc2);
                acc3 = fmaf(hv, w2[(ob + 3) * 384 + lane + j * 32], acc3);
            }
            #pragma unroll
            for (int off = 16; off; off >>= 1) {
                acc0 += __shfl_xor_sync(FULLM, acc0, off);
                acc1 += __shfl_xor_sync(FULLM, acc1, off);
                acc2 += __shfl_xor_sync(FULLM, acc2, off);
                acc3 += __shfl_xor_sync(FULLM, acc3, off);
            }
            if (lane == 0) {
                #pragma unroll
                for (int u = 0; u < 4; u++) {
                    float a = (u == 0 ? acc0 : u == 1 ? acc1 : u == 2 ? acc2 : acc3) + b2[ob + u];
                    float gamma = 1.f / (1.f + expf(-a));
                    float rms = sqrtf(g_sums[192 + ob + u] * (1.0f / 4096.0f) + 1e-6f);
                    g_mult[ob + u] = scale[ob + u] * gamma / rms;
                }
            }
        }
    }
    __syncthreads();
    if (t < 192) { g_sums[t] = 0.f; g_sums[192 + t] = 0.f; }
}

// ---------------- GEMM v3: out = epi(W(Co,Ci) @ X(Ci,N) + bias) --------------
// Block tile 64(m) x 128(n), 256 threads, 4x8 outputs per thread (f32x2 accums).
// Register-prefetch pipelining over K-tiles of 16.
// XN:   X stored as (N,Ci) instead of (Ci,N)
// EPI:  0 none, 1 exact gelu, 2 +res (res in (Co,N) layout)
// WS:   scale W rows' k-entries by g_mult[k] at load (adaRMSNorm fold)
// STATS: accumulate per-channel sum/sumsq of outputs into g_sums (atomicAdd)
// OUTNCO: write (N,Co) instead of (Co,N)
template <int CI, bool XN, int EPI, bool WS, bool STATS, bool OUTNCO>
__global__ void __launch_bounds__(256)
gemm_kernel(const float* __restrict__ W, const float* __restrict__ X,
            const float* __restrict__ bias, const float* __restrict__ res,
            float* __restrict__ out, int Co, int N) {
    __shared__ float sW[16][68];    // [k][m]
    __shared__ float sX[16][136];   // [k][n]
    const int NK = CI / 16;

    const int bn = blockIdx.x * 128;
    const int bm = blockIdx.y * 64;
    const int tid = threadIdx.x;
    const int tx = tid & 15;
    const int ty = tid >> 4;

    // staging thread roles
    const int wk = tid & 15, wm = tid >> 4;       // W: k, m-base
    float regW[4];
    float4 regX4[2];    // XN=false path
    float regXs[8];     // XN=true path

    unsigned long long acc[4][4];
    #pragma unroll
    for (int i = 0; i < 4; i++)
        #pragma unroll
        for (int q = 0; q < 4; q++) acc[i][q] = 0ull;

    auto loadTile = [&](int kk) {
        float gm = WS ? g_mult[kk + wk] : 1.f;
        #pragma unroll
        for (int r = 0; r < 4; r++)
            regW[r] = W[(size_t)(bm + wm + r * 16) * CI + kk + wk] * gm;
        if (XN) {
            #pragma unroll
            for (int r = 0; r < 8; r++)
                regXs[r] = X[(size_t)(bn + wm + r * 16) * CI + kk + wk];
        } else {
            #pragma unroll
            for (int i = 0; i < 2; i++) {
                int fi = tid + i * 256;
                int k = fi >> 5, n4 = fi & 31;
                regX4[i] = *(const float4*)(X + (size_t)(kk + k) * N + bn + n4 * 4);
            }
        }
    };
    auto storeTile = [&]() {
        #pragma unroll
        for (int r = 0; r < 4; r++) sW[wk][wm + r * 16] = regW[r];
        if (XN) {
            #pragma unroll
            for (int r = 0; r < 8; r++) sX[wk][wm + r * 16] = regXs[r];
        } else {
            #pragma unroll
            for (int i = 0; i < 2; i++) {
                int fi = tid + i * 256;
                int k = fi >> 5, n4 = fi & 31;
                *(float4*)&sX[k][n4 * 4] = regX4[i];
            }
        }
    };

    loadTile(0);
    storeTile();
    __syncthreads();

    #pragma unroll 1
    for (int t = 0; t < NK; t++) {
        if (t + 1 < NK) loadTile((t + 1) * 16);
        #pragma unroll
        for (int k = 0; k < 16; k++) {
            float4 a = *(const float4*)&sW[k][ty * 4];
            ulonglong2 B0 = *(const ulonglong2*)&sX[k][tx * 4];
            ulonglong2 B1 = *(const ulonglong2*)&sX[k][64 + tx * 4];
            unsigned long long ax = dupf2(a.x), ay = dupf2(a.y),
                               az = dupf2(a.z), aw = dupf2(a.w);
            fmaf2(acc[0][0], ax, B0.x); fmaf2(acc[0][1], ax, B0.y);
            fmaf2(acc[0][2], ax, B1.x); fmaf2(acc[0][3], ax, B1.y);
            fmaf2(acc[1][0], ay, B0.x); fmaf2(acc[1][1], ay, B0.y);
            fmaf2(acc[1][2], ay, B1.x); fmaf2(acc[1][3], ay, B1.y);
            fmaf2(acc[2][0], az, B0.x); fmaf2(acc[2][1], az, B0.y);
            fmaf2(acc[2][2], az, B1.x); fmaf2(acc[2][3], az, B1.y);
            fmaf2(acc[3][0], aw, B0.x); fmaf2(acc[3][1], aw, B0.y);
            fmaf2(acc[3][2], aw, B1.x); fmaf2(acc[3][3], aw, B1.y);
        }
        __syncthreads();
        if (t + 1 < NK) {
            storeTile();
            __syncthreads();
        }
    }

    // ---- epilogue ----
    float vv[4][8];
    #pragma unroll
    for (int i = 0; i < 4; i++) {
        int m = bm + ty * 4 + i;
        float bv = bias[m];
        #pragma unroll
        for (int q = 0; q < 4; q++) {
            float2 u = unpackf2(acc[i][q]);
            vv[i][q * 2 + 0] = u.x + bv;
            vv[i][q * 2 + 1] = u.y + bv;
        }
        if (EPI == 1) {
            #pragma unroll
            for (int j = 0; j < 8; j++) {
                float v = vv[i][j];
                vv[i][j] = v * 0.5f * (1.f + erff(v * 0.70710678118654752f));
            }
        }
        if (EPI == 2) {
            float4 r0 = *(const float4*)&res[(size_t)m * N + bn + tx * 4];
            float4 r1 = *(const float4*)&res[(size_t)m * N + bn + 64 + tx * 4];
            vv[i][0] += r0.x; vv[i][1] += r0.y; vv[i][2] += r0.z; vv[i][3] += r0.w;
            vv[i][4] += r1.x; vv[i][5] += r1.y; vv[i][6] += r1.z; vv[i][7] += r1.w;
        }
        if (STATS) {
            float ls = 0.f, ls2 = 0.f;
            #pragma unroll
            for (int j = 0; j < 8; j++) { ls += vv[i][j]; ls2 = fmaf(vv[i][j], vv[i][j], ls2); }
            #pragma unroll
            for (int off = 8; off; off >>= 1) {
                ls  += __shfl_down_sync(FULLM, ls, off, 16);
                ls2 += __shfl_down_sync(FULLM, ls2, off, 16);
            }
            if ((tid & 15) == 0) {
                atomicAdd(&g_sums[m], ls);
                atomicAdd(&g_sums[192 + m], ls2);
            }
        }
        if (!OUTNCO) {
            *(float4*)&out[(size_t)m * N + bn + tx * 4]      = *(float4*)&vv[i][0];
            *(float4*)&out[(size_t)m * N + bn + 64 + tx * 4] = *(float4*)&vv[i][4];
        }
    }
    if (OUTNCO) {
        #pragma unroll
        for (int j = 0; j < 8; j++) {
            int n = bn + (j >> 2) * 64 + tx * 4 + (j & 3);
            float4 o4 = make_float4(vv[0][j], vv[1][j], vv[2][j], vv[3][j]);
            *(float4*)&out[(size_t)n * Co + bm + ty * 4] = o4;
        }
    }
}

// ---------------- 3D neighborhood attention (tiled) ---------------------------
#define KV_STRIDE 36
__device__ __forceinline__ void load_kv_tile(float* sKV, const float* __restrict__ src,
                                             int Bd, int Bh, int Bw, int tid) {
    #pragma unroll
    for (int it = 0; it < 16; it++) {
        int i = tid + it * 256;
        int row = i >> 3, g = i & 7;
        int rd = row >> 6, rh = (row >> 3) & 7, rw = row & 7;
        int gpos = ((Bd + rd) << 8) + ((Bh + rh) << 4) + (Bw + rw);
        float4 val = *(const float4*)(src + (size_t)gpos * 576 + g * 4);
        int q = g >> 1, c2 = (g & 1) * 4;
        *(float4*)&sKV[row * KV_STRIDE + ((q ^ (row & 3)) << 3) + c2] = val;
    }
}

__global__ void __launch_bounds__(256) attn_kernel(const float* __restrict__ qkv,
                                                   float* __restrict__ o) {
    extern __shared__ float sKV[];
    const int tile = blockIdx.x, head = blockIdx.y;
    const int Td = ((tile >> 4) & 3) * 4, Th = ((tile >> 2) & 3) * 4, Tw = (tile & 3) * 4;
    const int Bd = min(max(Td - 2, 0), 8);
    const int Bh = min(max(Th - 2, 0), 8);
    const int Bw = min(max(Tw - 2, 0), 8);

    const int tid = threadIdx.x;
    const int quarter = tid & 3, vox = tid >> 2;
    const int aw = vox & 3, ah = (vox >> 2) & 3, ad = vox >> 4;
    const int vd = Td + ad, vh = Th + ah, vw = Tw + aw;
    const int gv = (vd << 8) + (vh << 4) + vw;
    const int ld = min(max(vd - 2, 0), 11) - Bd;
    const int lh = min(max(vh - 2, 0), 11) - Bh;
    const int lw = min(max(vw - 2, 0), 11) - Bw;
    const int rbase = ld * 64 + lh * 8 + lw;
    const int lane = tid & 31;

    float q[8];
    {
        const float* qp = qkv + (size_t)gv * 576 + head * 32 + quarter * 8;
        #pragma unroll
        for (int c = 0; c < 8; c++) q[c] = qp[c] * 0.17677669529663687f;
    }

    load_kv_tile(sKV, qkv + 192 + head * 32, Bd, Bh, Bw, tid);
    __syncthreads();

    float sc[32];
    #pragma unroll
    for (int i = 0; i < 32; i++) sc[i] = -1e30f;

    #pragma unroll
    for (int j = 0; j < 125; j++) {
        const int a = j / 25, b = (j / 5) % 5, c5 = j % 5;
        int row = rbase + a * 64 + b * 8 + c5;
        int cb = row * KV_STRIDE + ((quarter ^ (row & 3)) << 3);
        float4 k0 = *(const float4*)&sKV[cb];
        float4 k1 = *(const float4*)&sKV[cb + 4];
        float p = q[0] * k0.x;
        p = fmaf(q[1], k0.y, p); p = fmaf(q[2], k0.z, p); p = fmaf(q[3], k0.w, p);
        p = fmaf(q[4], k1.x, p); p = fmaf(q[5], k1.y, p);
        p = fmaf(q[6], k1.z, p); p = fmaf(q[7], k1.w, p);
        p += __shfl_xor_sync(FULLM, p, 1);
        p += __shfl_xor_sync(FULLM, p, 2);
        if ((j & 3) == quarter) sc[j >> 2] = p;
    }

    float mx = -1e30f;
    #pragma unroll
    for (int i = 0; i < 32; i++) mx = fmaxf(mx, sc[i]);
    mx = fmaxf(mx, __shfl_xor_sync(FULLM, mx, 1));
    mx = fmaxf(mx, __shfl_xor_sync(FULLM, mx, 2));
    float tot = 0.f;
    #pragma unroll
    for (int i = 0; i < 32; i++) { sc[i] = __expf(sc[i] - mx); tot += sc[i]; }
    tot += __shfl_xor_sync(FULLM, tot, 1);
    tot += __shfl_xor_sync(FULLM, tot, 2);
    float inv = 1.f / tot;

    __syncthreads();
    load_kv_tile(sKV, qkv + 384 + head * 32, Bd, Bh, Bw, tid);
    __syncthreads();

    float o8[8] = {0.f, 0.f, 0.f, 0.f, 0.f, 0.f, 0.f, 0.f};
    #pragma unroll
    for (int j = 0; j < 125; j++) {
        const int a = j / 25, b = (j / 5) % 5, c5 = j % 5;
        float p = __shfl_sync(FULLM, sc[j >> 2], (lane & ~3) | (j & 3));
        int row = rbase + a * 64 + b * 8 + c5;
        int cb = row * KV_STRIDE + ((quarter ^ (row & 3)) << 3);
        float4 v0 = *(const float4*)&sKV[cb];
        float4 v1 = *(const float4*)&sKV[cb + 4];
        o8[0] = fmaf(p, v0.x, o8[0]); o8[1] = fmaf(p, v0.y, o8[1]);
        o8[2] = fmaf(p, v0.z, o8[2]); o8[3] = fmaf(p, v0.w, o8[3]);
        o8[4] = fmaf(p, v1.x, o8[4]); o8[5] = fmaf(p, v1.y, o8[5]);
        o8[6] = fmaf(p, v1.z, o8[6]); o8[7] = fmaf(p, v1.w, o8[7]);
    }
    float* op = o + (size_t)gv * 192 + head * 32 + quarter * 8;
    #pragma unroll
    for (int c = 0; c < 8; c++) op[c] = o8[c] * inv;
}

// ---------------- orchestration ----------------------------------------------
extern "C" void kernel_launch(void* const* d_in, const int* in_sizes, int n_in,
                              void* d_out, int out_size) {
    const float* x      = (const float*)d_in[0];
    const float* scale1 = (const float*)d_in[1];
    const float* n1_w1  = (const float*)d_in[2];
    const float* n1_b1  = (const float*)d_in[3];
    const float* n1_w2  = (const float*)d_in[4];
    const float* n1_b2  = (const float*)d_in[5];
    const float* qkv_w  = (const float*)d_in[6];
    const float* qkv_b  = (const float*)d_in[7];
    const float* proj_w = (const float*)d_in[8];
    const float* proj_b = (const float*)d_in[9];
    const float* scale2 = (const float*)d_in[10];
    const float* n2_w1  = (const float*)d_in[11];
    const float* n2_b1  = (const float*)d_in[12];
    const float* n2_w2  = (const float*)d_in[13];
    const float* n2_b2  = (const float*)d_in[14];
    const float* mlp_w1 = (const float*)d_in[15];
    const float* mlp_b1 = (const float*)d_in[16];
    const float* mlp_w2 = (const float*)d_in[17];
    const float* mlp_b2 = (const float*)d_in[18];
    float* out = (float*)d_out;

    float *qkv, *ob, *x2, *mb;
    cudaGetSymbolAddress((void**)&qkv, g_qkv);
    cudaGetSymbolAddress((void**)&ob,  g_o);
    cudaGetSymbolAddress((void**)&x2,  g_x2);
    cudaGetSymbolAddress((void**)&mb,  g_m);

    cudaFuncSetAttribute(attn_kernel, cudaFuncAttributeMaxDynamicSharedMemorySize,
                         512 * KV_STRIDE * 4);

    // ---- stage A ----
    colstats_kernel<<<192, 256>>>(x);
    gamma_kernel<<<1, 384>>>(n1_w1, n1_b1, n1_w2, n1_b2, scale1);  // zeroes g_sums after

    // qkv: (576,192)@(192,4096) -> (4096,576) pos-major
    gemm_kernel<192, false, 0, true, false, true><<<dim3(32, 9), 256>>>(
        qkv_w, x, qkv_b, nullptr, qkv, 576, NPOS);

    // attention -> O (4096,192) pos-major
    attn_kernel<<<dim3(64, 6), 256, 512 * KV_STRIDE * 4>>>(qkv, ob);

    // proj + residual + fused stage-B colstats: x2 (C,N)
    gemm_kernel<192, true, 2, false, true, false><<<dim3(32, 3), 256>>>(
        proj_w, ob, proj_b, x, x2, 192, NPOS);

    // ---- stage B ----
    gamma_kernel<<<1, 384>>>(n2_w1, n2_b1, n2_w2, n2_b2, scale2);

    // mlp1 + gelu: (768,192)@(192,4096) -> (768,4096)
    gemm_kernel<192, false, 1, true, false, false><<<dim3(32, 12), 256>>>(
        mlp_w1, x2, mlp_b1, nullptr, mb, 768, NPOS);

    // mlp2 + residual -> final output (C,N) == (1,192,16,16,16)
    gemm_kernel<768, false, 2, false, false, false><<<dim3(32, 3), 256>>>(
        mlp_w2, mb, mlp_b2, x2, out, 192, NPOS);
}